// round 11
// baseline (speedup 1.0000x reference)
#include <cuda_runtime.h>
#include <cuda_fp16.h>
#include <cstdint>

// out[m][d] = sum_k ecg[m*128+k] * W[d*128+k] + b[d],  M=196608, K=128, N=64.
// 2-term fp16 HMMA: D = A16*Whi + A16*Wlo (W split hi+lo fp16, fp32 accum).
// This revision targets the L1 wavefront budget:
//  - warp m-tile 64 rows: each ldmatrix feeds 16 MMAs (W smem reads halved)
//  - epilogue staged through smem (reusing W region) -> coalesced STG.128

#define THREADS 128
#define BM 256           // 4 warps x 64 rows
#define WPAD 136         // fp16 per padded W row (272 B -> conflict-free ldmatrix)
#define STG_STRIDE 72    // staging row stride in floats (conflict-free)

__device__ __forceinline__ uint32_t s2u(const void* p) {
    uint32_t a;
    asm("{ .reg .u64 t; cvta.to.shared.u64 t, %1; cvt.u32.u64 %0, t; }" : "=r"(a) : "l"(p));
    return a;
}

__device__ __forceinline__ uint32_t f16x2(float x, float y) {
    uint32_t r;
    asm("cvt.rn.f16x2.f32 %0, %1, %2;" : "=r"(r) : "f"(y), "f"(x));
    return r;
}

__device__ __forceinline__ void split2h(float x, float y, uint32_t& hi, uint32_t& lo) {
    hi = f16x2(x, y);
    __half2 h = *reinterpret_cast<__half2*>(&hi);
    float2 hf = __half22float2(h);
    lo = f16x2(x - hf.x, y - hf.y);
}

__device__ __forceinline__ void ldsm4(uint32_t* r, uint32_t addr) {
    asm volatile("ldmatrix.sync.aligned.m8n8.x4.shared.b16 {%0,%1,%2,%3}, [%4];"
                 : "=r"(r[0]), "=r"(r[1]), "=r"(r[2]), "=r"(r[3]) : "r"(addr));
}

__device__ __forceinline__ void mma16816h(float* c,
                                          uint32_t a0, uint32_t a1, uint32_t a2, uint32_t a3,
                                          uint32_t b0, uint32_t b1) {
    asm volatile(
        "mma.sync.aligned.m16n8k16.row.col.f32.f16.f16.f32 "
        "{%0,%1,%2,%3}, {%4,%5,%6,%7}, {%8,%9}, {%0,%1,%2,%3};"
        : "+f"(c[0]), "+f"(c[1]), "+f"(c[2]), "+f"(c[3])
        : "r"(a0), "r"(a1), "r"(a2), "r"(a3), "r"(b0), "r"(b1));
}

__global__ __launch_bounds__(THREADS, 2)
void ecg_tok_mma(const float* __restrict__ ecg,
                 const float* __restrict__ W,
                 const float* __restrict__ bias,
                 float* __restrict__ out,
                 long long xelems, int fillCount) {
    // W hi/lo tiles; after the mainloop the same region is reused as the
    // epilogue staging buffer (one __syncthreads separates the two uses).
    __shared__ __align__(16) char smem_raw[2 * 64 * WPAD * 2];
    uint32_t* Whi32 = reinterpret_cast<uint32_t*>(smem_raw);
    uint32_t* Wlo32 = Whi32 + 64 * WPAD / 2;

    const int tid  = threadIdx.x;
    const int warp = tid >> 5;
    const int lane = tid & 31;
    const long long m0 = (long long)blockIdx.x * BM;

    // ---- folded fill: beat_intervals tail ----
    {
        int fi = blockIdx.x * THREADS + tid;
        if (fi < fillCount) out[xelems + fi] = 128.0f;
    }

    // ---- prologue: load + split W (fp16 hi/lo) with per-16-chunk column perm ----
    #pragma unroll
    for (int it = 0; it < 16; it++) {
        int idx   = tid + it * THREADS;     // 0..2047
        int n     = idx >> 5;
        int r     = idx & 31;
        int chunk = r >> 2;
        int q     = r & 3;
        float4 v = *reinterpret_cast<const float4*>(W + n * 128 + chunk * 16 + q * 4);
        uint32_t h0, l0, h1, l1;
        split2h(v.x, v.y, h0, l0);
        split2h(v.z, v.w, h1, l1);
        int u = n * (WPAD / 2) + chunk * 8 + q;
        Whi32[u]     = h0;
        Whi32[u + 4] = h1;
        Wlo32[u]     = l0;
        Wlo32[u + 4] = l1;
    }
    __syncthreads();

    // ldmatrix lane addressing
    const int lm_row  = ((lane >> 4) << 3) + (lane & 7);
    const int lm_kofs = ((lane >> 3) & 1) << 4;   // bytes
    const uint32_t lm_term  = (uint32_t)(lm_row * (WPAD * 2) + lm_kofs);
    const uint32_t whi_base = s2u(Whi32) + lm_term;
    const uint32_t wlo_base = s2u(Wlo32) + lm_term;

    // A geometry: warp rows = warp*64 + {0..63}; lane float4 at col 4*(lane&3)
    const int arow = warp * 64 + (lane >> 2);
    const float* abase = ecg + (m0 + arow) * 128 + 4 * (lane & 3);

    float acc[4][8][4];
    #pragma unroll
    for (int f = 0; f < 4; f++)
        #pragma unroll
        for (int nt = 0; nt < 8; nt++)
            #pragma unroll
            for (int j = 0; j < 4; j++) acc[f][nt][j] = 0.0f;

    // A prefetch (1-deep): cur[j] = row offset 8*j, k-step s
    float4 cur[8];
    #pragma unroll
    for (int j = 0; j < 8; j++)
        cur[j] = *reinterpret_cast<const float4*>(abase + j * 8 * 128);

    #pragma unroll
    for (int s = 0; s < 8; s++) {
        // convert current A chunk to fp16 fragments
        uint32_t ah[16];
        #pragma unroll
        for (int j = 0; j < 8; j++) {
            ah[2 * j]     = f16x2(cur[j].x, cur[j].y);
            ah[2 * j + 1] = f16x2(cur[j].z, cur[j].w);
        }

        if (s < 7) {
            #pragma unroll
            for (int j = 0; j < 8; j++)
                cur[j] = *reinterpret_cast<const float4*>(
                    abase + (s + 1) * 16 + j * 8 * 128);
        }

        #pragma unroll
        for (int ntp = 0; ntp < 4; ntp++) {
            const uint32_t off = (uint32_t)(ntp * 16 * WPAD * 2 + s * 32);
            uint32_t bh[4], bl[4];
            ldsm4(bh, whi_base + off);
            ldsm4(bl, wlo_base + off);

            // frag f: a0=ah[4f], a1=ah[4f+2], a2=ah[4f+1], a3=ah[4f+3]
            #pragma unroll
            for (int f = 0; f < 4; f++) {
                mma16816h(acc[f][2 * ntp],     ah[4*f], ah[4*f+2], ah[4*f+1], ah[4*f+3],
                          bh[0], bh[1]);
                mma16816h(acc[f][2 * ntp + 1], ah[4*f], ah[4*f+2], ah[4*f+1], ah[4*f+3],
                          bh[2], bh[3]);
            }
            #pragma unroll
            for (int f = 0; f < 4; f++) {
                mma16816h(acc[f][2 * ntp],     ah[4*f], ah[4*f+2], ah[4*f+1], ah[4*f+3],
                          bl[0], bl[1]);
                mma16816h(acc[f][2 * ntp + 1], ah[4*f], ah[4*f+2], ah[4*f+1], ah[4*f+3],
                          bl[2], bl[3]);
            }
        }
    }

    // ---- epilogue: stage per-warp in smem (reuses W region), coalesced STG ----
    __syncthreads();   // all warps done reading W smem

    float* stage = reinterpret_cast<float*>(smem_raw) + warp * (16 * STG_STRIDE);
    const float4 bv4 = reinterpret_cast<const float4*>(bias)[lane & 15];
    const int r0 = lane >> 2;
    const int c0 = 2 * (lane & 3);
    const int rr = lane >> 4;        // 0/1
    const int cc = lane & 15;        // float4 col index

    #pragma unroll
    for (int f = 0; f < 4; f++) {
        __syncwarp();
        #pragma unroll
        for (int nt = 0; nt < 8; nt++) {
            *reinterpret_cast<float2*>(&stage[STG_STRIDE * r0 + 8 * nt + c0]) =
                make_float2(acc[f][nt][0], acc[f][nt][1]);
            *reinterpret_cast<float2*>(&stage[STG_STRIDE * (r0 + 8) + 8 * nt + c0]) =
                make_float2(acc[f][nt][2], acc[f][nt][3]);
        }
        __syncwarp();

        const long long rowbase = m0 + warp * 64 + f * 16;
        #pragma unroll
        for (int i = 0; i < 8; i++) {
            int r = 2 * i + rr;
            float4 v = *reinterpret_cast<float4*>(&stage[STG_STRIDE * r + 4 * cc]);
            v.x += bv4.x; v.y += bv4.y; v.z += bv4.z; v.w += bv4.w;
            *reinterpret_cast<float4*>(out + (rowbase + r) * 64 + 4 * cc) = v;
        }
    }
}

extern "C" void kernel_launch(void* const* d_in, const int* in_sizes, int n_in,
                              void* d_out, int out_size) {
    const float* ecg = (const float*)d_in[0];
    const float* W   = (const float*)d_in[1];
    const float* b   = (const float*)d_in[2];
    float* out = (float*)d_out;

    const int M = in_sizes[0] / 128;
    const long long xelems = (long long)M * 64;
    const int fillCount = out_size - (int)xelems;

    ecg_tok_mma<<<M / BM, THREADS>>>(ecg, W, b, out, xelems, fillCount);
}